// round 10
// baseline (speedup 1.0000x reference)
#include <cuda_runtime.h>
#include <cuda_fp16.h>
#include <cstdint>
#include <cstddef>

// ---------------------------------------------------------------------------
// RGCN 2-layer, mean agg, ReLU, L2 norm. N=100000, E=1600000, R=2, 128->128->64.
// Round 10: all GEMM A-operands fp16 (no split terms), h kept fp16-only,
// normalize fused into combine2 epilogue, uint2 gather loads.
// ---------------------------------------------------------------------------

#define NN   100000
#define NE   1600000
#define NREL 2
#define CIN  128
#define CHID 128
#define COUT 64

#define SCAN_N (NREL * NN)                  // 200000 buckets
#define SBS    512
#define SNB    ((SCAN_N + SBS - 1) / SBS)   // 391

// Scratch (static device globals; no allocation allowed).
__device__ __align__(128) __half g_agg16[(size_t)NREL * NN * CIN]; // 51.2 MB
__device__ __align__(128) __half g_h16[(size_t)NN * CHID];         // 25.6 MB
__device__ __align__(128) __half g_x16[(size_t)NN * CIN];          // 25.6 MB
__device__ int g_icnt[SCAN_N];
__device__ int g_off[SCAN_N];
__device__ int g_cur[SCAN_N];
__device__ int g_bsum[SNB];
__device__ int g_srcs[NE];
__device__ int g_is64;

// ---------------------------------------------------------------------------
// Edge dtype detection (jax x64-disabled silently downcasts int64 -> int32).
// ---------------------------------------------------------------------------
__global__ void detect_kernel(const void* et) {
    const long long* p = (const long long*)et;
    int ok = 1;
    for (int i = 0; i < 512; i++) {
        long long v = p[i];
        if (v < 0 || v >= NREL) { ok = 0; break; }
    }
    g_is64 = ok;
}

__device__ __forceinline__ long long ld_idx(const void* p, long long i, int is64) {
    if (is64) return ((const long long*)p)[i];
    return (long long)((const int*)p)[i];
}

// ---------------------------------------------------------------------------
// x -> fp16 copy (once).
// ---------------------------------------------------------------------------
__global__ void cvt_x_kernel(const float* __restrict__ x) {
    size_t i = (size_t)blockIdx.x * blockDim.x + threadIdx.x;   // word of 2
    const size_t n2 = (size_t)NN * CIN / 2;
    if (i >= n2) return;
    float2 v = ((const float2*)x)[i];
    __half2 h = __floats2half2_rn(v.x, v.y);
    ((__half2*)g_x16)[i] = h;
}

// ---------------------------------------------------------------------------
// CSR build: count -> 2-level scan -> place.
// ---------------------------------------------------------------------------
__global__ void zero_icnt_kernel() {
    int i = blockIdx.x * blockDim.x + threadIdx.x;
    if (i < SCAN_N) g_icnt[i] = 0;
}

__global__ void count_kernel(const void* ei, const void* et) {
    int e = blockIdx.x * blockDim.x + threadIdx.x;
    if (e >= NE) return;
    int is64 = g_is64;
    int dst = (int)ld_idx(ei, (long long)NE + e, is64);
    int r   = (int)ld_idx(et, e, is64);
    atomicAdd(&g_icnt[r * NN + dst], 1);
}

__global__ void scan1_kernel() {
    __shared__ int s[SBS];
    int tid = threadIdx.x;
    int i = blockIdx.x * SBS + tid;
    int v = (i < SCAN_N) ? g_icnt[i] : 0;
    s[tid] = v;
    __syncthreads();
#pragma unroll
    for (int o = 1; o < SBS; o <<= 1) {
        int t = 0;
        if (tid >= o) t = s[tid - o];
        __syncthreads();
        if (tid >= o) s[tid] += t;
        __syncthreads();
    }
    if (i < SCAN_N) g_off[i] = s[tid] - v;
    if (tid == SBS - 1) g_bsum[blockIdx.x] = s[SBS - 1];
}

__global__ void scan2_kernel() {
    __shared__ int s[SBS];
    int tid = threadIdx.x;
    int v = (tid < SNB) ? g_bsum[tid] : 0;
    s[tid] = v;
    __syncthreads();
#pragma unroll
    for (int o = 1; o < SBS; o <<= 1) {
        int t = 0;
        if (tid >= o) t = s[tid - o];
        __syncthreads();
        if (tid >= o) s[tid] += t;
        __syncthreads();
    }
    if (tid < SNB) g_bsum[tid] = s[tid] - v;
}

__global__ void scan3_kernel() {
    int i = blockIdx.x * blockDim.x + threadIdx.x;
    if (i >= SCAN_N) return;
    int o = g_off[i] + g_bsum[i / SBS];
    g_off[i] = o;
    g_cur[i] = o;
}

__global__ void place_kernel(const void* ei, const void* et) {
    int e = blockIdx.x * blockDim.x + threadIdx.x;
    if (e >= NE) return;
    int is64 = g_is64;
    int src = (int)ld_idx(ei, e, is64);
    int dst = (int)ld_idx(ei, (long long)NE + e, is64);
    int r   = (int)ld_idx(et, e, is64);
    int p = atomicAdd(&g_cur[r * NN + dst], 1);
    g_srcs[p] = src;
}

// ---------------------------------------------------------------------------
// Gather-aggregate over fp16 rows: one warp per (rel,node) bucket.
// Lane l owns one uint2 (4 halves, 8B) per row. fp32 accumulate, fp16 store.
// ---------------------------------------------------------------------------
__global__ void gather_kernel(int use_h) {
    int gt = blockIdx.x * blockDim.x + threadIdx.x;
    int w = gt >> 5;
    int lane = gt & 31;
    if (w >= SCAN_N) return;
    const uint2* __restrict__ base = (const uint2*)(use_h ? g_h16 : g_x16);
    int off = g_off[w];
    int cnt = g_icnt[w];
    float2 a0 = make_float2(0.f, 0.f), a1 = a0;
    int e = 0;
    for (; e + 4 <= cnt; e += 4) {
#pragma unroll
        for (int u = 0; u < 4; u++) {
            int sN = g_srcs[off + e + u];
            uint2 p = base[(size_t)sN * 32 + lane];
            float2 f0 = __half22float2(*(__half2*)&p.x);
            float2 f1 = __half22float2(*(__half2*)&p.y);
            a0.x += f0.x; a0.y += f0.y;
            a1.x += f1.x; a1.y += f1.y;
        }
    }
    for (; e < cnt; e++) {
        int sN = g_srcs[off + e];
        uint2 p = base[(size_t)sN * 32 + lane];
        float2 f0 = __half22float2(*(__half2*)&p.x);
        float2 f1 = __half22float2(*(__half2*)&p.y);
        a0.x += f0.x; a0.y += f0.y;
        a1.x += f1.x; a1.y += f1.y;
    }
    float s = 1.0f / (float)(cnt > 0 ? cnt : 1);
    __half2 o0 = __floats2half2_rn(a0.x * s, a0.y * s);
    __half2 o1 = __floats2half2_rn(a1.x * s, a1.y * s);
    uint2 o;
    o.x = *(uint32_t*)&o0;
    o.y = *(uint32_t*)&o1;
    ((uint2*)g_agg16)[(size_t)w * 32 + lane] = o;
}

// ---------------------------------------------------------------------------
// fp16 helpers.
// ---------------------------------------------------------------------------
__device__ __forceinline__ uint32_t packh2(float a, float b) {
    __half2 h = __floats2half2_rn(a, b);
    return *(uint32_t*)&h;
}

__device__ __forceinline__ void mma_f16(float* c, uint32_t a0, uint32_t a1,
                                        uint32_t a2, uint32_t a3,
                                        uint32_t b0, uint32_t b1) {
    asm volatile(
        "mma.sync.aligned.m16n8k16.row.col.f32.f16.f16.f32 "
        "{%0,%1,%2,%3}, {%4,%5,%6,%7}, {%8,%9}, {%0,%1,%2,%3};"
        : "+f"(c[0]), "+f"(c[1]), "+f"(c[2]), "+f"(c[3])
        : "r"(a0), "r"(a1), "r"(a2), "r"(a3), "r"(b0), "r"(b1));
}

// ---------------------------------------------------------------------------
// Fused combine GEMM, all-fp16 A operands (single-term MMA):
//   out = act( [root | agg0 | agg1] @ [Wroot;Wrel0;Wrel1] + b )
// Layer 1: root = x16, out -> g_h16 (relu, fp16).
// Layer 2: root = h16, out -> d_out with fused L2 normalization.
// 256 threads = 8 warps; warp w owns rows [16w,16w+16) x OUTC cols.
// K=384 in 12 chunks of 32.
// ---------------------------------------------------------------------------
template <int OUTC, bool LAYER1>
__global__ void __launch_bounds__(256)
combine_mma_kernel(const float* __restrict__ Wroot,
                   const float* __restrict__ Wrel,
                   const float* __restrict__ bias,
                   float* __restrict__ out_param) {
    constexpr int NT = OUTC / 8;
    __shared__ uint32_t As[128][20];      // [row][k-word], 2 f16/word, pad 4
    __shared__ uint32_t Bs[OUTC][20];     // [n][k-word], fp16

    int tid  = threadIdx.x;
    int wid  = tid >> 5;
    int lane = tid & 31;
    int m0   = blockIdx.x * 128;
    int mrow = wid * 16;

    float acc[NT][4];
#pragma unroll
    for (int i = 0; i < NT; i++)
#pragma unroll
        for (int j = 0; j < 4; j++) acc[i][j] = 0.f;

    for (int c = 0; c < 12; c++) {
        int seg  = c >> 2;            // 0: root features, 1/2: relation means
        int krel = (c & 3) * 32;

        if (tid < 128) {
            // A loader: thread t = row t; 32 halves = 4 uint4, raw copy.
            const __half* Ab = (seg == 0) ? (LAYER1 ? g_x16 : g_h16)
                                          : (g_agg16 + (size_t)(seg - 1) * NN * 128);
            int node = m0 + tid;
            bool valid = (node < NN);
            const uint4* src = (const uint4*)(Ab + (size_t)node * 128 + krel);
#pragma unroll
            for (int i = 0; i < 4; i++) {
                uint4 v = valid ? src[i] : make_uint4(0u, 0u, 0u, 0u);
                As[tid][4 * i + 0] = v.x;
                As[tid][4 * i + 1] = v.y;
                As[tid][4 * i + 2] = v.z;
                As[tid][4 * i + 3] = v.w;
            }
        } else if (tid - 128 < OUTC) {
            // B loader: thread owns output col n; transpose W[k][n] -> [n][k].
            const float* Bsrc = (seg == 0) ? Wroot : (Wrel + (size_t)(seg - 1) * 128 * OUTC);
            int n = tid - 128;
#pragma unroll
            for (int g = 0; g < 16; g++) {
                float v0 = Bsrc[(size_t)(krel + 2 * g + 0) * OUTC + n];
                float v1 = Bsrc[(size_t)(krel + 2 * g + 1) * OUTC + n];
                Bs[n][g] = packh2(v0, v1);
            }
        }
        __syncthreads();

#pragma unroll
        for (int k16 = 0; k16 < 2; k16++) {
            int wk = k16 * 8 + (lane & 3);
            int r0 = mrow + (lane >> 2);
            uint32_t a0 = As[r0][wk],     a1 = As[r0 + 8][wk];
            uint32_t a2 = As[r0][wk + 4], a3 = As[r0 + 8][wk + 4];
#pragma unroll
            for (int n8 = 0; n8 < NT; n8++) {
                int nr = n8 * 8 + (lane >> 2);
                uint32_t b0 = Bs[nr][wk], b1 = Bs[nr][wk + 4];
                mma_f16(acc[n8], a0, a1, a2, a3, b0, b1);
            }
        }
        __syncthreads();
    }

    // Epilogue. Fragment map: c0={r0, col}, c1={r0, col+1}, c2/c3 at r0+8.
    int r0 = m0 + mrow + (lane >> 2);

    if (LAYER1) {
        // ReLU, write fp16 h rows (one uint32 = 2 cols).
#pragma unroll
        for (int n8 = 0; n8 < NT; n8++) {
            int col = n8 * 8 + 2 * (lane & 3);
            float b0 = bias[col], b1 = bias[col + 1];
            float o0x = fmaxf(acc[n8][0] + b0, 0.f), o0y = fmaxf(acc[n8][1] + b1, 0.f);
            float o1x = fmaxf(acc[n8][2] + b0, 0.f), o1y = fmaxf(acc[n8][3] + b1, 0.f);
            if (r0 < NN)
                *((uint32_t*)g_h16 + (size_t)r0 * 64 + col / 2) = packh2(o0x, o0y);
            if (r0 + 8 < NN)
                *((uint32_t*)g_h16 + (size_t)(r0 + 8) * 64 + col / 2) = packh2(o1x, o1y);
        }
    } else {
        // Fused bias + L2 normalize. The 4 threads of a quad jointly own all
        // OUTC=64 cols of rows r0 and r0+8 -> quad shfl reduction.
        float ss0 = 0.f, ss1 = 0.f;
#pragma unroll
        for (int n8 = 0; n8 < NT; n8++) {
            int col = n8 * 8 + 2 * (lane & 3);
            float b0 = bias[col], b1 = bias[col + 1];
            acc[n8][0] += b0; acc[n8][1] += b1;
            acc[n8][2] += b0; acc[n8][3] += b1;
            ss0 += acc[n8][0] * acc[n8][0] + acc[n8][1] * acc[n8][1];
            ss1 += acc[n8][2] * acc[n8][2] + acc[n8][3] * acc[n8][3];
        }
        ss0 += __shfl_xor_sync(0xFFFFFFFFu, ss0, 1);
        ss0 += __shfl_xor_sync(0xFFFFFFFFu, ss0, 2);
        ss1 += __shfl_xor_sync(0xFFFFFFFFu, ss1, 1);
        ss1 += __shfl_xor_sync(0xFFFFFFFFu, ss1, 2);
        float s0 = 1.0f / fmaxf(sqrtf(ss0), 1e-12f);
        float s1 = 1.0f / fmaxf(sqrtf(ss1), 1e-12f);
#pragma unroll
        for (int n8 = 0; n8 < NT; n8++) {
            int col = n8 * 8 + 2 * (lane & 3);
            if (r0 < NN)
                *(float2*)(out_param + (size_t)r0 * OUTC + col) =
                    make_float2(acc[n8][0] * s0, acc[n8][1] * s0);
            if (r0 + 8 < NN)
                *(float2*)(out_param + (size_t)(r0 + 8) * OUTC + col) =
                    make_float2(acc[n8][2] * s1, acc[n8][3] * s1);
        }
    }
}

// ---------------------------------------------------------------------------
extern "C" void kernel_launch(void* const* d_in, const int* in_sizes, int n_in,
                              void* d_out, int out_size) {
    const float* x       = (const float*)d_in[0];
    const void*  ei      = d_in[1];
    const void*  et      = d_in[2];
    const float* W1_rel  = (const float*)d_in[3];
    const float* W1_root = (const float*)d_in[4];
    const float* b1      = (const float*)d_in[5];
    const float* W2_rel  = (const float*)d_in[6];
    const float* W2_root = (const float*)d_in[7];
    const float* b2      = (const float*)d_in[8];
    float* out = (float*)d_out;

    const int MT = (NN + 127) / 128;   // 782

    detect_kernel<<<1, 1>>>(et);
    cvt_x_kernel<<<(int)(((size_t)NN * CIN / 2 + 255) / 256), 256>>>(x);

    // CSR build (once; reused by both layers)
    zero_icnt_kernel<<<(SCAN_N + 255) / 256, 256>>>();
    count_kernel<<<(NE + 255) / 256, 256>>>(ei, et);
    scan1_kernel<<<SNB, SBS>>>();
    scan2_kernel<<<1, SBS>>>();
    scan3_kernel<<<(SCAN_N + 255) / 256, 256>>>();
    place_kernel<<<(NE + 255) / 256, 256>>>(ei, et);

    // Layer 1: gather(x16) -> combine (relu) -> h16
    gather_kernel<<<SCAN_N * 32 / 256, 256>>>(0);
    combine_mma_kernel<CHID, true><<<MT, 256>>>(W1_root, W1_rel, b1, nullptr);

    // Layer 2: gather(h16) -> combine + fused L2 normalize -> out
    gather_kernel<<<SCAN_N * 32 / 256, 256>>>(1);
    combine_mma_kernel<COUT, false><<<MT, 256>>>(W2_root, W2_rel, b2, out);
}

// round 14
// speedup vs baseline: 1.4504x; 1.4504x over previous
#include <cuda_runtime.h>
#include <cuda_fp16.h>
#include <cstdint>
#include <cstddef>

// ---------------------------------------------------------------------------
// RGCN 2-layer, mean agg, ReLU, L2 norm. N=100000, E=1600000, R=2, 128->128->64.
// Round 11: R10 structure (all-fp16 A operands, fused normalize) + software-
// pipelined combine GEMM (double-buffered smem, prefetch into registers).
// ---------------------------------------------------------------------------

#define NN   100000
#define NE   1600000
#define NREL 2
#define CIN  128
#define CHID 128
#define COUT 64

#define SCAN_N (NREL * NN)                  // 200000 buckets
#define SBS    512
#define SNB    ((SCAN_N + SBS - 1) / SBS)   // 391

// Scratch (static device globals; no allocation allowed).
__device__ __align__(128) __half g_agg16[(size_t)NREL * NN * CIN]; // 51.2 MB
__device__ __align__(128) __half g_h16[(size_t)NN * CHID];         // 25.6 MB
__device__ __align__(128) __half g_x16[(size_t)NN * CIN];          // 25.6 MB
__device__ int g_icnt[SCAN_N];
__device__ int g_off[SCAN_N];
__device__ int g_cur[SCAN_N];
__device__ int g_bsum[SNB];
__device__ int g_srcs[NE];
__device__ int g_is64;

// ---------------------------------------------------------------------------
// Edge dtype detection (jax x64-disabled silently downcasts int64 -> int32).
// ---------------------------------------------------------------------------
__global__ void detect_kernel(const void* et) {
    const long long* p = (const long long*)et;
    int ok = 1;
    for (int i = 0; i < 512; i++) {
        long long v = p[i];
        if (v < 0 || v >= NREL) { ok = 0; break; }
    }
    g_is64 = ok;
}

__device__ __forceinline__ long long ld_idx(const void* p, long long i, int is64) {
    if (is64) return ((const long long*)p)[i];
    return (long long)((const int*)p)[i];
}

// ---------------------------------------------------------------------------
// x -> fp16 copy (once).
// ---------------------------------------------------------------------------
__global__ void cvt_x_kernel(const float* __restrict__ x) {
    size_t i = (size_t)blockIdx.x * blockDim.x + threadIdx.x;   // word of 2
    const size_t n2 = (size_t)NN * CIN / 2;
    if (i >= n2) return;
    float2 v = ((const float2*)x)[i];
    __half2 h = __floats2half2_rn(v.x, v.y);
    ((__half2*)g_x16)[i] = h;
}

// ---------------------------------------------------------------------------
// CSR build: count -> 2-level scan -> place.
// ---------------------------------------------------------------------------
__global__ void zero_icnt_kernel() {
    int i = blockIdx.x * blockDim.x + threadIdx.x;
    if (i < SCAN_N) g_icnt[i] = 0;
}

__global__ void count_kernel(const void* ei, const void* et) {
    int e = blockIdx.x * blockDim.x + threadIdx.x;
    if (e >= NE) return;
    int is64 = g_is64;
    int dst = (int)ld_idx(ei, (long long)NE + e, is64);
    int r   = (int)ld_idx(et, e, is64);
    atomicAdd(&g_icnt[r * NN + dst], 1);
}

__global__ void scan1_kernel() {
    __shared__ int s[SBS];
    int tid = threadIdx.x;
    int i = blockIdx.x * SBS + tid;
    int v = (i < SCAN_N) ? g_icnt[i] : 0;
    s[tid] = v;
    __syncthreads();
#pragma unroll
    for (int o = 1; o < SBS; o <<= 1) {
        int t = 0;
        if (tid >= o) t = s[tid - o];
        __syncthreads();
        if (tid >= o) s[tid] += t;
        __syncthreads();
    }
    if (i < SCAN_N) g_off[i] = s[tid] - v;
    if (tid == SBS - 1) g_bsum[blockIdx.x] = s[SBS - 1];
}

__global__ void scan2_kernel() {
    __shared__ int s[SBS];
    int tid = threadIdx.x;
    int v = (tid < SNB) ? g_bsum[tid] : 0;
    s[tid] = v;
    __syncthreads();
#pragma unroll
    for (int o = 1; o < SBS; o <<= 1) {
        int t = 0;
        if (tid >= o) t = s[tid - o];
        __syncthreads();
        if (tid >= o) s[tid] += t;
        __syncthreads();
    }
    if (tid < SNB) g_bsum[tid] = s[tid] - v;
}

__global__ void scan3_kernel() {
    int i = blockIdx.x * blockDim.x + threadIdx.x;
    if (i >= SCAN_N) return;
    int o = g_off[i] + g_bsum[i / SBS];
    g_off[i] = o;
    g_cur[i] = o;
}

__global__ void place_kernel(const void* ei, const void* et) {
    int e = blockIdx.x * blockDim.x + threadIdx.x;
    if (e >= NE) return;
    int is64 = g_is64;
    int src = (int)ld_idx(ei, e, is64);
    int dst = (int)ld_idx(ei, (long long)NE + e, is64);
    int r   = (int)ld_idx(et, e, is64);
    int p = atomicAdd(&g_cur[r * NN + dst], 1);
    g_srcs[p] = src;
}

// ---------------------------------------------------------------------------
// Gather-aggregate over fp16 rows: one warp per (rel,node) bucket.
// Lane l owns one uint2 (4 halves, 8B) per row. fp32 accumulate, fp16 store.
// ---------------------------------------------------------------------------
__global__ void gather_kernel(int use_h) {
    int gt = blockIdx.x * blockDim.x + threadIdx.x;
    int w = gt >> 5;
    int lane = gt & 31;
    if (w >= SCAN_N) return;
    const uint2* __restrict__ base = (const uint2*)(use_h ? g_h16 : g_x16);
    int off = g_off[w];
    int cnt = g_icnt[w];
    float2 a0 = make_float2(0.f, 0.f), a1 = a0;
    int e = 0;
    for (; e + 4 <= cnt; e += 4) {
#pragma unroll
        for (int u = 0; u < 4; u++) {
            int sN = g_srcs[off + e + u];
            uint2 p = base[(size_t)sN * 32 + lane];
            float2 f0 = __half22float2(*(__half2*)&p.x);
            float2 f1 = __half22float2(*(__half2*)&p.y);
            a0.x += f0.x; a0.y += f0.y;
            a1.x += f1.x; a1.y += f1.y;
        }
    }
    for (; e < cnt; e++) {
        int sN = g_srcs[off + e];
        uint2 p = base[(size_t)sN * 32 + lane];
        float2 f0 = __half22float2(*(__half2*)&p.x);
        float2 f1 = __half22float2(*(__half2*)&p.y);
        a0.x += f0.x; a0.y += f0.y;
        a1.x += f1.x; a1.y += f1.y;
    }
    float s = 1.0f / (float)(cnt > 0 ? cnt : 1);
    __half2 o0 = __floats2half2_rn(a0.x * s, a0.y * s);
    __half2 o1 = __floats2half2_rn(a1.x * s, a1.y * s);
    uint2 o;
    o.x = *(uint32_t*)&o0;
    o.y = *(uint32_t*)&o1;
    ((uint2*)g_agg16)[(size_t)w * 32 + lane] = o;
}

// ---------------------------------------------------------------------------
// fp16 helpers.
// ---------------------------------------------------------------------------
__device__ __forceinline__ uint32_t packh2(float a, float b) {
    __half2 h = __floats2half2_rn(a, b);
    return *(uint32_t*)&h;
}

__device__ __forceinline__ void mma_f16(float* c, uint32_t a0, uint32_t a1,
                                        uint32_t a2, uint32_t a3,
                                        uint32_t b0, uint32_t b1) {
    asm volatile(
        "mma.sync.aligned.m16n8k16.row.col.f32.f16.f16.f32 "
        "{%0,%1,%2,%3}, {%4,%5,%6,%7}, {%8,%9}, {%0,%1,%2,%3};"
        : "+f"(c[0]), "+f"(c[1]), "+f"(c[2]), "+f"(c[3])
        : "r"(a0), "r"(a1), "r"(a2), "r"(a3), "r"(b0), "r"(b1));
}

// ---------------------------------------------------------------------------
// Fused combine GEMM, all-fp16 A operands, software-pipelined:
//   out = act( [root | agg0 | agg1] @ [Wroot;Wrel0;Wrel1] + b )
// Double-buffered smem; next chunk's global loads issued into registers
// before the MMA block (latency overlap); one __syncthreads per chunk.
// Layer 1: root = x16, out -> g_h16 (relu, fp16).
// Layer 2: root = h16, out -> d_out with fused L2 normalization.
// ---------------------------------------------------------------------------
template <int OUTC, bool LAYER1>
__global__ void __launch_bounds__(256)
combine_mma_kernel(const float* __restrict__ Wroot,
                   const float* __restrict__ Wrel,
                   const float* __restrict__ bias,
                   float* __restrict__ out_param) {
    constexpr int NT = OUTC / 8;
    __shared__ uint32_t As[2][128][20];    // [buf][row][k-word], pad 4
    __shared__ uint32_t Bs[2][OUTC][20];   // [buf][n][k-word]

    int tid  = threadIdx.x;
    int wid  = tid >> 5;
    int lane = tid & 31;
    int m0   = blockIdx.x * 128;
    int mrow = wid * 16;

    bool isA = (tid < 128);
    int  bn  = tid - 128;                  // B col for loader threads
    bool isB = (!isA) && (bn < OUTC);
    int  node = m0 + tid;                  // A loader row
    bool valid = isA && (node < NN);

    float acc[NT][4];
#pragma unroll
    for (int i = 0; i < NT; i++)
#pragma unroll
        for (int j = 0; j < 4; j++) acc[i][j] = 0.f;

    uint4    ra[4];
    uint32_t rb[16];

    // Loader: fetch chunk c's tile into registers.
    auto load_regs = [&](int c) {
        int seg  = c >> 2;
        int krel = (c & 3) * 32;
        if (isA) {
            const __half* Ab = (seg == 0) ? (LAYER1 ? g_x16 : g_h16)
                                          : (g_agg16 + (size_t)(seg - 1) * NN * 128);
            const uint4* src = (const uint4*)(Ab + (size_t)node * 128 + krel);
#pragma unroll
            for (int i = 0; i < 4; i++)
                ra[i] = valid ? src[i] : make_uint4(0u, 0u, 0u, 0u);
        } else if (isB) {
            const float* Bsrc = (seg == 0) ? Wroot : (Wrel + (size_t)(seg - 1) * 128 * OUTC);
#pragma unroll
            for (int g = 0; g < 16; g++) {
                float v0 = Bsrc[(size_t)(krel + 2 * g + 0) * OUTC + bn];
                float v1 = Bsrc[(size_t)(krel + 2 * g + 1) * OUTC + bn];
                rb[g] = packh2(v0, v1);
            }
        }
    };
    auto store_smem = [&](int buf) {
        if (isA) {
#pragma unroll
            for (int i = 0; i < 4; i++) {
                As[buf][tid][4 * i + 0] = ra[i].x;
                As[buf][tid][4 * i + 1] = ra[i].y;
                As[buf][tid][4 * i + 2] = ra[i].z;
                As[buf][tid][4 * i + 3] = ra[i].w;
            }
        } else if (isB) {
#pragma unroll
            for (int g = 0; g < 16; g++) Bs[buf][bn][g] = rb[g];
        }
    };

    load_regs(0);
    store_smem(0);
    __syncthreads();

    for (int c = 0; c < 12; c++) {
        int cur = c & 1;
        if (c < 11) load_regs(c + 1);      // global latency overlaps MMA

#pragma unroll
        for (int k16 = 0; k16 < 2; k16++) {
            int wk = k16 * 8 + (lane & 3);
            int r0 = mrow + (lane >> 2);
            uint32_t a0 = As[cur][r0][wk],     a1 = As[cur][r0 + 8][wk];
            uint32_t a2 = As[cur][r0][wk + 4], a3 = As[cur][r0 + 8][wk + 4];
#pragma unroll
            for (int n8 = 0; n8 < NT; n8++) {
                int nr = n8 * 8 + (lane >> 2);
                uint32_t b0 = Bs[cur][nr][wk], b1 = Bs[cur][nr][wk + 4];
                mma_f16(acc[n8], a0, a1, a2, a3, b0, b1);
            }
        }

        if (c < 11) store_smem(cur ^ 1);
        __syncthreads();
    }

    // Epilogue. Fragment map: c0={r0, col}, c1={r0, col+1}, c2/c3 at r0+8.
    int r0 = m0 + mrow + (lane >> 2);

    if (LAYER1) {
        // ReLU, write fp16 h rows (one uint32 = 2 cols).
#pragma unroll
        for (int n8 = 0; n8 < NT; n8++) {
            int col = n8 * 8 + 2 * (lane & 3);
            float b0 = bias[col], b1 = bias[col + 1];
            float o0x = fmaxf(acc[n8][0] + b0, 0.f), o0y = fmaxf(acc[n8][1] + b1, 0.f);
            float o1x = fmaxf(acc[n8][2] + b0, 0.f), o1y = fmaxf(acc[n8][3] + b1, 0.f);
            if (r0 < NN)
                *((uint32_t*)g_h16 + (size_t)r0 * 64 + col / 2) = packh2(o0x, o0y);
            if (r0 + 8 < NN)
                *((uint32_t*)g_h16 + (size_t)(r0 + 8) * 64 + col / 2) = packh2(o1x, o1y);
        }
    } else {
        // Fused bias + L2 normalize: quad of threads owns all 64 cols of a row.
        float ss0 = 0.f, ss1 = 0.f;
#pragma unroll
        for (int n8 = 0; n8 < NT; n8++) {
            int col = n8 * 8 + 2 * (lane & 3);
            float b0 = bias[col], b1 = bias[col + 1];
            acc[n8][0] += b0; acc[n8][1] += b1;
            acc[n8][2] += b0; acc[n8][3] += b1;
            ss0 += acc[n8][0] * acc[n8][0] + acc[n8][1] * acc[n8][1];
            ss1 += acc[n8][2] * acc[n8][2] + acc[n8][3] * acc[n8][3];
        }
        ss0 += __shfl_xor_sync(0xFFFFFFFFu, ss0, 1);
        ss0 += __shfl_xor_sync(0xFFFFFFFFu, ss0, 2);
        ss1 += __shfl_xor_sync(0xFFFFFFFFu, ss1, 1);
        ss1 += __shfl_xor_sync(0xFFFFFFFFu, ss1, 2);
        float s0 = 1.0f / fmaxf(sqrtf(ss0), 1e-12f);
        float s1 = 1.0f / fmaxf(sqrtf(ss1), 1e-12f);
#pragma unroll
        for (int n8 = 0; n8 < NT; n8++) {
            int col = n8 * 8 + 2 * (lane & 3);
            if (r0 < NN)
                *(float2*)(out_param + (size_t)r0 * OUTC + col) =
                    make_float2(acc[n8][0] * s0, acc[n8][1] * s0);
            if (r0 + 8 < NN)
                *(float2*)(out_param + (size_t)(r0 + 8) * OUTC + col) =
                    make_float2(acc[n8][2] * s1, acc[n8][3] * s1);
        }
    }
}

// ---------------------------------------------------------------------------
extern "C" void kernel_launch(void* const* d_in, const int* in_sizes, int n_in,
                              void* d_out, int out_size) {
    const float* x       = (const float*)d_in[0];
    const void*  ei      = d_in[1];
    const void*  et      = d_in[2];
    const float* W1_rel  = (const float*)d_in[3];
    const float* W1_root = (const float*)d_in[4];
    const float* b1      = (const float*)d_in[5];
    const float* W2_rel  = (const float*)d_in[6];
    const float* W2_root = (const float*)d_in[7];
    const float* b2      = (const float*)d_in[8];
    float* out = (float*)d_out;

    const int MT = (NN + 127) / 128;   // 782

    detect_kernel<<<1, 1>>>(et);
    cvt_x_kernel<<<(int)(((size_t)NN * CIN / 2 + 255) / 256), 256>>>(x);

    // CSR build (once; reused by both layers)
    zero_icnt_kernel<<<(SCAN_N + 255) / 256, 256>>>();
    count_kernel<<<(NE + 255) / 256, 256>>>(ei, et);
    scan1_kernel<<<SNB, SBS>>>();
    scan2_kernel<<<1, SBS>>>();
    scan3_kernel<<<(SCAN_N + 255) / 256, 256>>>();
    place_kernel<<<(NE + 255) / 256, 256>>>(ei, et);

    // Layer 1: gather(x16) -> combine (relu) -> h16
    gather_kernel<<<SCAN_N * 32 / 256, 256>>>(0);
    combine_mma_kernel<CHID, true><<<MT, 256>>>(W1_root, W1_rel, b1, nullptr);

    // Layer 2: gather(h16) -> combine + fused L2 normalize -> out
    gather_kernel<<<SCAN_N * 32 / 256, 256>>>(1);
    combine_mma_kernel<COUT, false><<<MT, 256>>>(W2_root, W2_rel, b2, out);
}

// round 16
// speedup vs baseline: 1.5040x; 1.0370x over previous
#include <cuda_runtime.h>
#include <cuda_fp16.h>
#include <cstdint>
#include <cstddef>

// ---------------------------------------------------------------------------
// RGCN 2-layer, mean agg, ReLU, L2 norm. N=100000, E=1600000, R=2, 128->128->64.
// Round 15: ldmatrix fragment loads + 32x64 warp retile in combines,
// parallel detect, memset for icnt. Numerics unchanged from R14.
// ---------------------------------------------------------------------------

#define NN   100000
#define NE   1600000
#define NREL 2
#define CIN  128
#define CHID 128
#define COUT 64

#define SCAN_N (NREL * NN)                  // 200000 buckets
#define SBS    512
#define SNB    ((SCAN_N + SBS - 1) / SBS)   // 391

// Scratch (static device globals; no allocation allowed).
__device__ __align__(128) __half g_agg16[(size_t)NREL * NN * CIN]; // 51.2 MB
__device__ __align__(128) __half g_h16[(size_t)NN * CHID];         // 25.6 MB
__device__ __align__(128) __half g_x16[(size_t)NN * CIN];          // 25.6 MB
__device__ int g_icnt[SCAN_N];
__device__ int g_off[SCAN_N];
__device__ int g_cur[SCAN_N];
__device__ int g_bsum[SNB];
__device__ int g_srcs[NE];
__device__ int g_is64;

// ---------------------------------------------------------------------------
// Edge dtype detection (jax x64-disabled silently downcasts int64 -> int32).
// Parallel: 512 threads each check one int64; benign-race flag.
// ---------------------------------------------------------------------------
__global__ void detect_kernel(const void* et) {
    __shared__ int bad;
    if (threadIdx.x == 0) bad = 0;
    __syncthreads();
    const long long* p = (const long long*)et;
    long long v = p[threadIdx.x];
    if (v < 0 || v >= NREL) bad = 1;
    __syncthreads();
    if (threadIdx.x == 0) g_is64 = !bad;
}

__device__ __forceinline__ long long ld_idx(const void* p, long long i, int is64) {
    if (is64) return ((const long long*)p)[i];
    return (long long)((const int*)p)[i];
}

// ---------------------------------------------------------------------------
// x -> fp16 copy (once).
// ---------------------------------------------------------------------------
__global__ void cvt_x_kernel(const float* __restrict__ x) {
    size_t i = (size_t)blockIdx.x * blockDim.x + threadIdx.x;   // word of 2
    const size_t n2 = (size_t)NN * CIN / 2;
    if (i >= n2) return;
    float2 v = ((const float2*)x)[i];
    __half2 h = __floats2half2_rn(v.x, v.y);
    ((__half2*)g_x16)[i] = h;
}

// ---------------------------------------------------------------------------
// CSR build: count -> 2-level scan -> place. (icnt zeroed via memset.)
// ---------------------------------------------------------------------------
__global__ void count_kernel(const void* ei, const void* et) {
    int e = blockIdx.x * blockDim.x + threadIdx.x;
    if (e >= NE) return;
    int is64 = g_is64;
    int dst = (int)ld_idx(ei, (long long)NE + e, is64);
    int r   = (int)ld_idx(et, e, is64);
    atomicAdd(&g_icnt[r * NN + dst], 1);
}

__global__ void scan1_kernel() {
    __shared__ int s[SBS];
    int tid = threadIdx.x;
    int i = blockIdx.x * SBS + tid;
    int v = (i < SCAN_N) ? g_icnt[i] : 0;
    s[tid] = v;
    __syncthreads();
#pragma unroll
    for (int o = 1; o < SBS; o <<= 1) {
        int t = 0;
        if (tid >= o) t = s[tid - o];
        __syncthreads();
        if (tid >= o) s[tid] += t;
        __syncthreads();
    }
    if (i < SCAN_N) g_off[i] = s[tid] - v;
    if (tid == SBS - 1) g_bsum[blockIdx.x] = s[SBS - 1];
}

__global__ void scan2_kernel() {
    __shared__ int s[SBS];
    int tid = threadIdx.x;
    int v = (tid < SNB) ? g_bsum[tid] : 0;
    s[tid] = v;
    __syncthreads();
#pragma unroll
    for (int o = 1; o < SBS; o <<= 1) {
        int t = 0;
        if (tid >= o) t = s[tid - o];
        __syncthreads();
        if (tid >= o) s[tid] += t;
        __syncthreads();
    }
    if (tid < SNB) g_bsum[tid] = s[tid] - v;
}

__global__ void scan3_kernel() {
    int i = blockIdx.x * blockDim.x + threadIdx.x;
    if (i >= SCAN_N) return;
    int o = g_off[i] + g_bsum[i / SBS];
    g_off[i] = o;
    g_cur[i] = o;
}

__global__ void place_kernel(const void* ei, const void* et) {
    int e = blockIdx.x * blockDim.x + threadIdx.x;
    if (e >= NE) return;
    int is64 = g_is64;
    int src = (int)ld_idx(ei, e, is64);
    int dst = (int)ld_idx(ei, (long long)NE + e, is64);
    int r   = (int)ld_idx(et, e, is64);
    int p = atomicAdd(&g_cur[r * NN + dst], 1);
    g_srcs[p] = src;
}

// ---------------------------------------------------------------------------
// Gather-aggregate over fp16 rows: one warp per (rel,node) bucket.
// Lane l owns one uint2 (4 halves, 8B) per row. fp32 accumulate, fp16 store.
// ---------------------------------------------------------------------------
__global__ void gather_kernel(int use_h) {
    int gt = blockIdx.x * blockDim.x + threadIdx.x;
    int w = gt >> 5;
    int lane = gt & 31;
    if (w >= SCAN_N) return;
    const uint2* __restrict__ base = (const uint2*)(use_h ? g_h16 : g_x16);
    int off = g_off[w];
    int cnt = g_icnt[w];
    float2 a0 = make_float2(0.f, 0.f), a1 = a0;
    int e = 0;
    for (; e + 4 <= cnt; e += 4) {
#pragma unroll
        for (int u = 0; u < 4; u++) {
            int sN = g_srcs[off + e + u];
            uint2 p = base[(size_t)sN * 32 + lane];
            float2 f0 = __half22float2(*(__half2*)&p.x);
            float2 f1 = __half22float2(*(__half2*)&p.y);
            a0.x += f0.x; a0.y += f0.y;
            a1.x += f1.x; a1.y += f1.y;
        }
    }
    for (; e < cnt; e++) {
        int sN = g_srcs[off + e];
        uint2 p = base[(size_t)sN * 32 + lane];
        float2 f0 = __half22float2(*(__half2*)&p.x);
        float2 f1 = __half22float2(*(__half2*)&p.y);
        a0.x += f0.x; a0.y += f0.y;
        a1.x += f1.x; a1.y += f1.y;
    }
    float s = 1.0f / (float)(cnt > 0 ? cnt : 1);
    __half2 o0 = __floats2half2_rn(a0.x * s, a0.y * s);
    __half2 o1 = __floats2half2_rn(a1.x * s, a1.y * s);
    uint2 o;
    o.x = *(uint32_t*)&o0;
    o.y = *(uint32_t*)&o1;
    ((uint2*)g_agg16)[(size_t)w * 32 + lane] = o;
}

// ---------------------------------------------------------------------------
// fp16 helpers.
// ---------------------------------------------------------------------------
__device__ __forceinline__ uint32_t packh2(float a, float b) {
    __half2 h = __floats2half2_rn(a, b);
    return *(uint32_t*)&h;
}

__device__ __forceinline__ void mma_f16(float* c, uint32_t a0, uint32_t a1,
                                        uint32_t a2, uint32_t a3,
                                        uint32_t b0, uint32_t b1) {
    asm volatile(
        "mma.sync.aligned.m16n8k16.row.col.f32.f16.f16.f32 "
        "{%0,%1,%2,%3}, {%4,%5,%6,%7}, {%8,%9}, {%0,%1,%2,%3};"
        : "+f"(c[0]), "+f"(c[1]), "+f"(c[2]), "+f"(c[3])
        : "r"(a0), "r"(a1), "r"(a2), "r"(a3), "r"(b0), "r"(b1));
}

__device__ __forceinline__ void ldsm_x4(uint32_t& r0, uint32_t& r1,
                                        uint32_t& r2, uint32_t& r3,
                                        const uint32_t* p) {
    uint32_t a = (uint32_t)__cvta_generic_to_shared(p);
    asm volatile("ldmatrix.sync.aligned.m8n8.x4.shared.b16 {%0,%1,%2,%3}, [%4];"
                 : "=r"(r0), "=r"(r1), "=r"(r2), "=r"(r3) : "r"(a));
}

// ---------------------------------------------------------------------------
// Fused combine GEMM, all-fp16 A, software-pipelined, ldmatrix frag loads.
//   out = act( [root | agg0 | agg1] @ [Wroot;Wrel0;Wrel1] + b )
// Warp tiles: OUTC=128 -> 4m x 2n grid of 32x64 tiles (MW=2);
//             OUTC=64  -> 8m x 1n grid of 16x64 tiles (MW=1). NT=8 cols.
// Layer 1: root = x16, out -> g_h16 (relu, fp16).
// Layer 2: root = h16, out -> d_out with fused L2 normalization.
// ---------------------------------------------------------------------------
template <int OUTC, bool LAYER1>
__global__ void __launch_bounds__(256)
combine_mma_kernel(const float* __restrict__ Wroot,
                   const float* __restrict__ Wrel,
                   const float* __restrict__ bias,
                   float* __restrict__ out_param) {
    constexpr int WARPS_N = OUTC / 64;            // 2 or 1
    constexpr int MW      = (OUTC == 128) ? 2 : 1; // m16 tiles per warp
    constexpr int NT      = 8;                     // n8 tiles per warp (64 cols)
    __shared__ __align__(16) uint32_t As[2][128][20];   // [buf][row][k-word]
    __shared__ __align__(16) uint32_t Bs[2][OUTC][20];  // [buf][n][k-word]

    int tid  = threadIdx.x;
    int wid  = tid >> 5;
    int lane = tid & 31;
    int m0   = blockIdx.x * 128;
    int wm   = wid / WARPS_N;
    int wn   = wid % WARPS_N;
    int mrow = wm * (MW * 16);
    int ncol0 = wn * 64;

    bool isA = (tid < 128);
    int  bn  = tid - 128;                  // B col for loader threads
    bool isB = (!isA) && (bn < OUTC);
    int  node = m0 + tid;                  // A loader row
    bool valid = isA && (node < NN);

    float acc[MW][NT][4];
#pragma unroll
    for (int m = 0; m < MW; m++)
#pragma unroll
        for (int i = 0; i < NT; i++)
#pragma unroll
            for (int j = 0; j < 4; j++) acc[m][i][j] = 0.f;

    uint4    ra[4];
    uint32_t rb[16];

    auto load_regs = [&](int c) {
        int seg  = c >> 2;
        int krel = (c & 3) * 32;
        if (isA) {
            const __half* Ab = (seg == 0) ? (LAYER1 ? g_x16 : g_h16)
                                          : (g_agg16 + (size_t)(seg - 1) * NN * 128);
            const uint4* src = (const uint4*)(Ab + (size_t)node * 128 + krel);
#pragma unroll
            for (int i = 0; i < 4; i++)
                ra[i] = valid ? src[i] : make_uint4(0u, 0u, 0u, 0u);
        } else if (isB) {
            const float* Bsrc = (seg == 0) ? Wroot : (Wrel + (size_t)(seg - 1) * 128 * OUTC);
#pragma unroll
            for (int g = 0; g < 16; g++) {
                float v0 = Bsrc[(size_t)(krel + 2 * g + 0) * OUTC + bn];
                float v1 = Bsrc[(size_t)(krel + 2 * g + 1) * OUTC + bn];
                rb[g] = packh2(v0, v1);
            }
        }
    };
    auto store_smem = [&](int buf) {
        if (isA) {
#pragma unroll
            for (int i = 0; i < 4; i++) {
                As[buf][tid][4 * i + 0] = ra[i].x;
                As[buf][tid][4 * i + 1] = ra[i].y;
                As[buf][tid][4 * i + 2] = ra[i].z;
                As[buf][tid][4 * i + 3] = ra[i].w;
            }
        } else if (isB) {
#pragma unroll
            for (int g = 0; g < 16; g++) Bs[buf][bn][g] = rb[g];
        }
    };

    load_regs(0);
    store_smem(0);
    __syncthreads();

    // ldmatrix lane decomposition (x4: tile = lane>>3, row-in-tile = lane&7).
    int ltile = lane >> 3;
    int lrow  = lane & 7;

    for (int c = 0; c < 12; c++) {
        int cur = c & 1;
        if (c < 11) load_regs(c + 1);      // global latency overlaps MMA

#pragma unroll
        for (int k16 = 0; k16 < 2; k16++) {
            int kw = k16 * 8;
            // A fragments: per m16 tile, x4 = (r0-7,klo)(r8-15,klo)(r0-7,khi)(r8-15,khi)
            uint32_t af[MW][4];
#pragma unroll
            for (int m = 0; m < MW; m++) {
                const uint32_t* p = &As[cur][mrow + m * 16 + lrow + (ltile & 1) * 8]
                                       [kw + (ltile >> 1) * 4];
                ldsm_x4(af[m][0], af[m][1], af[m][2], af[m][3], p);
            }
            // B fragments: 4 x4 ops cover 8 n8 tiles (b0,b1 each).
            uint32_t bf[NT][2];
#pragma unroll
            for (int g = 0; g < 4; g++) {
                int n8 = 2 * g + (ltile >> 1);
                const uint32_t* p = &Bs[cur][ncol0 + n8 * 8 + lrow]
                                       [kw + (ltile & 1) * 4];
                uint32_t q0, q1, q2, q3;
                ldsm_x4(q0, q1, q2, q3, p);
                bf[2 * g + 0][0] = q0; bf[2 * g + 0][1] = q1;
                bf[2 * g + 1][0] = q2; bf[2 * g + 1][1] = q3;
            }
#pragma unroll
            for (int m = 0; m < MW; m++)
#pragma unroll
                for (int n8 = 0; n8 < NT; n8++)
                    mma_f16(acc[m][n8], af[m][0], af[m][1], af[m][2], af[m][3],
                            bf[n8][0], bf[n8][1]);
        }

        if (c < 11) store_smem(cur ^ 1);
        __syncthreads();
    }

    // Epilogue. Fragment map: c0={r0, col}, c1={r0, col+1}, c2/c3 at r0+8.
    if (LAYER1) {
#pragma unroll
        for (int m = 0; m < MW; m++) {
            int r0 = m0 + mrow + m * 16 + (lane >> 2);
#pragma unroll
            for (int n8 = 0; n8 < NT; n8++) {
                int col = ncol0 + n8 * 8 + 2 * (lane & 3);
                float b0 = bias[col], b1 = bias[col + 1];
                float o0x = fmaxf(acc[m][n8][0] + b0, 0.f);
                float o0y = fmaxf(acc[m][n8][1] + b1, 0.f);
                float o1x = fmaxf(acc[m][n8][2] + b0, 0.f);
                float o1y = fmaxf(acc[m][n8][3] + b1, 0.f);
                if (r0 < NN)
                    *((uint32_t*)g_h16 + (size_t)r0 * 64 + col / 2) = packh2(o0x, o0y);
                if (r0 + 8 < NN)
                    *((uint32_t*)g_h16 + (size_t)(r0 + 8) * 64 + col / 2) = packh2(o1x, o1y);
            }
        }
    } else {
        // OUTC=64: MW=1, wn=0; quad of threads owns all 64 cols of a row.
        int r0 = m0 + mrow + (lane >> 2);
        float ss0 = 0.f, ss1 = 0.f;
#pragma unroll
        for (int n8 = 0; n8 < NT; n8++) {
            int col = n8 * 8 + 2 * (lane & 3);
            float b0 = bias[col], b1 = bias[col + 1];
            acc[0][n8][0] += b0; acc[0][n8][1] += b1;
            acc[0][n8][2] += b0; acc[0][n8][3] += b1;
            ss0 += acc[0][n8][0] * acc[0][n8][0] + acc[0][n8][1] * acc[0][n8][1];
            ss1 += acc[0][n8][2] * acc[0][n8][2] + acc[0][n8][3] * acc[0][n8][3];
        }
        ss0 += __shfl_xor_sync(0xFFFFFFFFu, ss0, 1);
        ss0 += __shfl_xor_sync(0xFFFFFFFFu, ss0, 2);
        ss1 += __shfl_xor_sync(0xFFFFFFFFu, ss1, 1);
        ss1 += __shfl_xor_sync(0xFFFFFFFFu, ss1, 2);
        float s0 = 1.0f / fmaxf(sqrtf(ss0), 1e-12f);
        float s1 = 1.0f / fmaxf(sqrtf(ss1), 1e-12f);
#pragma unroll
        for (int n8 = 0; n8 < NT; n8++) {
            int col = n8 * 8 + 2 * (lane & 3);
            if (r0 < NN)
                *(float2*)(out_param + (size_t)r0 * OUTC + col) =
                    make_float2(acc[0][n8][0] * s0, acc[0][n8][1] * s0);
            if (r0 + 8 < NN)
                *(float2*)(out_param + (size_t)(r0 + 8) * OUTC + col) =
                    make_float2(acc[0][n8][2] * s1, acc[0][n8][3] * s1);
        }
    }
}

// ---------------------------------------------------------------------------
extern "C" void kernel_launch(void* const* d_in, const int* in_sizes, int n_in,
                              void* d_out, int out_size) {
    const float* x       = (const float*)d_in[0];
    const void*  ei      = d_in[1];
    const void*  et      = d_in[2];
    const float* W1_rel  = (const float*)d_in[3];
    const float* W1_root = (const float*)d_in[4];
    const float* b1      = (const float*)d_in[5];
    const float* W2_rel  = (const float*)d_in[6];
    const float* W2_root = (const float*)d_in[7];
    const float* b2      = (const float*)d_in[8];
    float* out = (float*)d_out;

    const int MT = (NN + 127) / 128;   // 782

    detect_kernel<<<1, 512>>>(et);
    cvt_x_kernel<<<(int)(((size_t)NN * CIN / 2 + 255) / 256), 256>>>(x);

    // CSR build (once; reused by both layers)
    void* icnt_ptr = nullptr;
    cudaGetSymbolAddress(&icnt_ptr, g_icnt);
    cudaMemsetAsync(icnt_ptr, 0, SCAN_N * sizeof(int));
    count_kernel<<<(NE + 255) / 256, 256>>>(ei, et);
    scan1_kernel<<<SNB, SBS>>>();
    scan2_kernel<<<1, SBS>>>();
    scan3_kernel<<<(SCAN_N + 255) / 256, 256>>>();
    place_kernel<<<(NE + 255) / 256, 256>>>(ei, et);

    // Layer 1: gather(x16) -> combine (relu) -> h16
    gather_kernel<<<SCAN_N * 32 / 256, 256>>>(0);
    combine_mma_kernel<CHID, true><<<MT, 256>>>(W1_root, W1_rel, b1, nullptr);

    // Layer 2: gather(h16) -> combine + fused L2 normalize -> out
    gather_kernel<<<SCAN_N * 32 / 256, 256>>>(1);
    combine_mma_kernel<COUT, false><<<MT, 256>>>(W2_root, W2_rel, b2, out);
}